// round 15
// baseline (speedup 1.0000x reference)
#include <cuda_runtime.h>
#include <cuda_fp16.h>
#include <cstdint>

#define NN 2048
#define DM 1024
#define NH 16
#define DK 64
#define LN_EPS 1e-5f
#define QKS 36   // u32 row stride for packed Q/K (32 pairs + 4 pad)

// Scratch (device globals) — fp16 pair arrays (u32 = f16x2)
__device__ uint32_t g_Xh[(size_t)NN * 512];
__device__ uint32_t g_Wq[(size_t)NH * 192 * 512];     // single fp16
__device__ uint32_t g_Wo[(size_t)DM * 512];           // single fp16
__device__ uint32_t g_Qh[(size_t)NH * NN * QKS];      // single fp16 (pre-scaled)
__device__ uint32_t g_Kh[(size_t)NH * NN * QKS];      // single fp16
__device__ uint32_t g_Vt[(size_t)NH * DK * (NN / 2)]; // fp16 [h][dk][keypair]
__device__ uint32_t g_Ch[(size_t)NN * 512];           // concat, single fp16
__device__ float    g_pre[(size_t)NN * DM];

// ---------------------------------------------------------------------------
// helpers
// ---------------------------------------------------------------------------
__device__ __forceinline__ uint32_t pack2h(float e0, float e1) {  // f16x2: e0 low
    uint32_t r;
    asm("cvt.rn.f16x2.f32 %0, %1, %2;" : "=r"(r) : "f"(e1), "f"(e0));
    return r;
}
__device__ __forceinline__ uint16_t f16bits(float v) {
    uint16_t u;
    asm("cvt.rn.f16.f32 %0, %1;" : "=h"(u) : "f"(v));
    return u;
}
__device__ __forceinline__ void mma_f16(float* c, const uint32_t* a, const uint32_t* b) {
    asm("mma.sync.aligned.m16n8k16.row.col.f32.f16.f16.f32 "
        "{%0,%1,%2,%3}, {%4,%5,%6,%7}, {%8,%9}, {%0,%1,%2,%3};\n"
        : "+f"(c[0]), "+f"(c[1]), "+f"(c[2]), "+f"(c[3])
        : "r"(a[0]), "r"(a[1]), "r"(a[2]), "r"(a[3]), "r"(b[0]), "r"(b[1]));
}
__device__ __forceinline__ void ldsm_x4(uint32_t* r, const uint32_t* p) {
    uint32_t addr = (uint32_t)__cvta_generic_to_shared(p);
    asm volatile("ldmatrix.sync.aligned.m8n8.x4.shared.b16 {%0,%1,%2,%3}, [%4];"
        : "=r"(r[0]), "=r"(r[1]), "=r"(r[2]), "=r"(r[3]) : "r"(addr));
}
#define CPA16(sptr, gptr) do {                                                 \
    uint32_t _s = (uint32_t)__cvta_generic_to_shared(sptr);                    \
    asm volatile("cp.async.cg.shared.global [%0], [%1], 16;" :: "r"(_s), "l"(gptr)); \
} while (0)
#define CP_COMMIT() asm volatile("cp.async.commit_group;")
#define CP_WAIT(n)  asm volatile("cp.async.wait_group %0;" :: "n"(n))

// ---------------------------------------------------------------------------
// fused conversion kernel: one launch for x, wqkv, wo
// blocks [0, 2048): x rows; [2048, 2816): wqkv tiles; [2816, 3072): wo tiles
// ---------------------------------------------------------------------------
__global__ void __launch_bounds__(256) conv_all_kernel(const float* __restrict__ x,
                                                       const float* __restrict__ wq,
                                                       const float* __restrict__ wk,
                                                       const float* __restrict__ wv,
                                                       const float* __restrict__ wo,
                                                       uint32_t* __restrict__ Xh,
                                                       uint32_t* __restrict__ Wq,
                                                       uint32_t* __restrict__ Wo)
{
    __shared__ float sw[64][65];
    const int b = blockIdx.x;
    const int t = threadIdx.x;

    if (b < NN) {
        float4 v = ((const float4*)x)[b * 256 + t];
        Xh[(size_t)b * 512 + 2 * t]     = pack2h(v.x, v.y);
        Xh[(size_t)b * 512 + 2 * t + 1] = pack2h(v.z, v.w);
        return;
    }
    if (b < NN + 768) {
        const int z  = b - NN;
        const int k0 = (z & 15) * 64;
        const int w  = z >> 4;            // 0..47
        const int sec = w >> 4, h = w & 15;
        const float* s = (sec == 0 ? wq : sec == 1 ? wk : wv) + (size_t)h * DM * DK;

        #pragma unroll
        for (int i = 0; i < 16; i++) {
            int idx = i * 256 + t;
            int row = idx >> 6, col = idx & 63;
            sw[row][col] = s[(size_t)(k0 + row) * DK + col];
        }
        __syncthreads();
        #pragma unroll
        for (int i = 0; i < 8; i++) {
            int idx = i * 256 + t;
            int n = idx >> 5, kp = idx & 31;
            size_t o = (size_t)h * (192 * 512) + (size_t)(sec * 64 + n) * 512 + k0 / 2 + kp;
            Wq[o] = pack2h(sw[2 * kp][n], sw[2 * kp + 1][n]);
        }
        return;
    }
    {
        const int z  = b - NN - 768;
        const int k0 = (z & 15) * 64;
        const int n0 = (z >> 4) * 64;

        #pragma unroll
        for (int i = 0; i < 16; i++) {
            int idx = i * 256 + t;
            int row = idx >> 6, col = idx & 63;
            sw[row][col] = wo[(size_t)(k0 + row) * DM + n0 + col];
        }
        __syncthreads();
        #pragma unroll
        for (int i = 0; i < 8; i++) {
            int idx = i * 256 + t;
            int n = idx >> 5, kp = idx & 31;
            size_t o = (size_t)(n0 + n) * 512 + k0 / 2 + kp;
            Wo[o] = pack2h(sw[2 * kp][n], sw[2 * kp + 1][n]);
        }
    }
}

// ---------------------------------------------------------------------------
// GEMM tile machinery: 128 rows x 64 cols, k-chunk 64, 3-stage cp.async,
// single __syncthreads per chunk. Rows stride-36 u32.
// Stage = A(128*36) + B(64*36) = 6912 u32; 3 stages = 82944 B.
// ---------------------------------------------------------------------------
#define G_STAGE_U32 6912
#define G_SMEM (3 * G_STAGE_U32 * 4)

__device__ __forceinline__ void gemm_stage_load(uint32_t* st,
                                                const uint32_t* Ag, const uint32_t* Bg,
                                                int kc32, int tid)
{
    #pragma unroll
    for (int i = 0; i < 4; i++) {
        int idx = tid + i * 256;               // 0..1023 : A rows 0..127
        int row = idx >> 3, blk = idx & 7;
        CPA16(st + row * 36 + blk * 4, Ag + (size_t)row * 512 + kc32 + blk * 4);
    }
    #pragma unroll
    for (int i = 0; i < 2; i++) {
        int idx = tid + i * 256;               // 0..511 : B rows 0..63
        int row = idx >> 3, blk = idx & 7;
        CPA16(st + 4608 + row * 36 + blk * 4, Bg + (size_t)row * 512 + kc32 + blk * 4);
    }
}

__device__ __forceinline__ void gemm_core(uint32_t* sm, float (*acc)[4],
                                          const uint32_t* Ag, const uint32_t* Bg,
                                          int tid, int aoff, int boff)
{
    gemm_stage_load(sm,               Ag, Bg, 0,  tid);
    CP_COMMIT();
    gemm_stage_load(sm + G_STAGE_U32, Ag, Bg, 32, tid);
    CP_COMMIT();

    for (int c = 0; c < 16; c++) {
        if (c < 15) { CP_WAIT(1); } else { CP_WAIT(0); }
        __syncthreads();
        if (c + 2 < 16) {
            gemm_stage_load(sm + ((c + 2) % 3) * G_STAGE_U32,
                            Ag, Bg, (c + 2) * 32, tid);
            CP_COMMIT();
        }

        const uint32_t* p  = sm + (c % 3) * G_STAGE_U32;
        const uint32_t* As = p;
        const uint32_t* Bs = p + 4608;

        #pragma unroll
        for (int ks = 0; ks < 4; ks++) {
            uint32_t a[4];
            ldsm_x4(a, As + aoff + ks * 8);
            #pragma unroll
            for (int nbp = 0; nbp < 4; nbp++) {
                uint32_t b[4];
                ldsm_x4(b, Bs + boff + nbp * 576 + ks * 8);
                mma_f16(acc[2 * nbp],     a, b);
                mma_f16(acc[2 * nbp + 1], a, b + 2);
            }
        }
    }
    __syncthreads();   // protect smem reuse by epilogue
}

// ---------------------------------------------------------------------------
// QKV GEMM: CTA = (row-tile, head, section). section: 0=Q, 1=K, 2=V.
// ---------------------------------------------------------------------------
__global__ void __launch_bounds__(256, 2) qkv_kernel(const uint32_t* __restrict__ Xh,
                                                     const uint32_t* __restrict__ W,
                                                     const float* __restrict__ qb,
                                                     const float* __restrict__ kb,
                                                     const float* __restrict__ vb,
                                                     uint32_t* __restrict__ oQh,
                                                     uint32_t* __restrict__ oKh,
                                                     uint32_t* __restrict__ oVt)
{
    extern __shared__ uint32_t sm[];
    const int m0  = blockIdx.x * 128;
    const int h   = blockIdx.y;
    const int sec = blockIdx.z;
    const int tid = threadIdx.x;
    const int wid = tid >> 5, lane = tid & 31, g = lane >> 2, t = lane & 3;
    const int lrow = lane & 7;
    const int aoff = (wid * 16 + lrow + ((lane >> 3) & 1) * 8) * 36 + (lane >> 4) * 4;
    const int boff = (lrow + ((lane >> 4) & 1) * 8) * 36 + ((lane >> 3) & 1) * 4;

    float acc[8][4] = {};

    gemm_core(sm, acc,
              Xh + (size_t)m0 * 512,
              W + ((size_t)h * 192 + sec * 64) * 512,
              tid, aoff, boff);

    const int r = wid * 16 + g;
    const int grow = m0 + r;

    if (sec == 0) {
        // Q: single fp16, pre-scaled 0.125
        #pragma unroll
        for (int nb = 0; nb < 8; nb++) {
            int col = nb * 8 + 2 * t;
            float b0 = qb[h * DK + col], b1 = qb[h * DK + col + 1];
            size_t base = ((size_t)h * NN + grow) * QKS + nb * 4 + t;
            oQh[base]           = pack2h((acc[nb][0] + b0) * 0.125f, (acc[nb][1] + b1) * 0.125f);
            oQh[base + 8 * QKS] = pack2h((acc[nb][2] + b0) * 0.125f, (acc[nb][3] + b1) * 0.125f);
        }
    } else if (sec == 1) {
        // K: single fp16
        #pragma unroll
        for (int nb = 0; nb < 8; nb++) {
            int col = nb * 8 + 2 * t;
            float b0 = kb[h * DK + col], b1 = kb[h * DK + col + 1];
            size_t base = ((size_t)h * NN + grow) * QKS + nb * 4 + t;
            oKh[base]           = pack2h(acc[nb][0] + b0, acc[nb][1] + b1);
            oKh[base + 8 * QKS] = pack2h(acc[nb][2] + b0, acc[nb][3] + b1);
        }
    } else {
        // V: fp16 transpose via smem ([64 dk][132 fp16] = stride 66 u32)
        uint16_t* Vs16 = (uint16_t*)sm;
        #pragma unroll
        for (int nb = 0; nb < 8; nb++) {
            int col = nb * 8 + 2 * t;
            float b0 = vb[h * DK + col], b1 = vb[h * DK + col + 1];
            Vs16[(col)     * 132 + r]     = f16bits(acc[nb][0] + b0);
            Vs16[(col + 1) * 132 + r]     = f16bits(acc[nb][1] + b1);
            Vs16[(col)     * 132 + r + 8] = f16bits(acc[nb][2] + b0);
            Vs16[(col + 1) * 132 + r + 8] = f16bits(acc[nb][3] + b1);
        }
        __syncthreads();
        #pragma unroll
        for (int i = 0; i < 16; i++) {
            int idx = tid + i * 256;
            int dk = idx >> 6, cc = idx & 63;
            oVt[((size_t)h * DK + dk) * (NN / 2) + m0 / 2 + cc] = sm[dk * 66 + cc];
        }
    }
}

// ---------------------------------------------------------------------------
// Out projection + bias + residual: CTA = (row-tile, 64-col tile). 1-term.
// ---------------------------------------------------------------------------
__global__ void __launch_bounds__(256, 2) outproj_kernel(const uint32_t* __restrict__ Ag,
                                                         const uint32_t* __restrict__ Bg,
                                                         const float* __restrict__ x,
                                                         const float* __restrict__ ob,
                                                         float* __restrict__ out)
{
    extern __shared__ uint32_t sm[];
    const int m0 = blockIdx.x * 128;
    const int c0 = blockIdx.y * 64;
    const int tid = threadIdx.x;
    const int wid = tid >> 5, lane = tid & 31, g = lane >> 2, t = lane & 3;
    const int lrow = lane & 7;
    const int aoff = (wid * 16 + lrow + ((lane >> 3) & 1) * 8) * 36 + (lane >> 4) * 4;
    const int boff = (lrow + ((lane >> 4) & 1) * 8) * 36 + ((lane >> 3) & 1) * 4;

    float acc[8][4] = {};

    gemm_core(sm, acc,
              Ag + (size_t)m0 * 512,
              Bg + (size_t)c0 * 512,
              tid, aoff, boff);

    const int r0 = m0 + wid * 16 + g;
    #pragma unroll
    for (int nb = 0; nb < 8; nb++) {
        int col = c0 + nb * 8 + 2 * t;
        float b0 = ob[col], b1 = ob[col + 1];
        const float* xr0 = &x[(size_t)r0 * DM + col];
        const float* xr1 = &x[(size_t)(r0 + 8) * DM + col];
        float2 v0 = make_float2(acc[nb][0] + b0 + xr0[0], acc[nb][1] + b1 + xr0[1]);
        float2 v1 = make_float2(acc[nb][2] + b0 + xr1[0], acc[nb][3] + b1 + xr1[1]);
        *(float2*)&out[(size_t)r0 * DM + col]       = v0;
        *(float2*)&out[(size_t)(r0 + 8) * DM + col] = v1;
    }
}

// ---------------------------------------------------------------------------
// Flash attention: fp16 QK (single-term) + fp16 PV, 3-stage pipeline,
// single sync per tile. buf = Kh[64][36] + Vt[64][36] = 4608 u32 per stage.
// ---------------------------------------------------------------------------
#define ATTN_BUF_U32 (2 * 64 * 36)
#define ATTN_SMEM_BYTES (3 * ATTN_BUF_U32 * 4)

__device__ __forceinline__ void attn_stage(uint32_t* dst, const uint32_t* Kh,
                                           const uint32_t* Vt,
                                           int h, int t0, int tid)
{
    const uint32_t* sKh = Kh + ((size_t)h * NN + t0) * QKS;
    const uint32_t* sVt = Vt + (size_t)h * DK * (NN / 2) + t0 / 2;
    for (int idx = tid; idx < 1088; idx += 256) {
        if (idx < 576) {
            CPA16(dst + idx * 4, sKh + idx * 4);
        } else {
            int j = idx - 576;
            int dk = j >> 3, c = (j & 7) * 4;
            CPA16(dst + 2304 + dk * 36 + c, sVt + (size_t)dk * (NN / 2) + c);
        }
    }
}

__global__ void __launch_bounds__(256, 2) attn_kernel(const uint32_t* __restrict__ Qh,
                                                      const uint32_t* __restrict__ Kh,
                                                      const uint32_t* __restrict__ Vt,
                                                      uint32_t* __restrict__ Ch)
{
    extern __shared__ uint32_t sm[];
    const int h  = blockIdx.y;
    const int q0 = blockIdx.x * 128;
    const int tid = threadIdx.x;
    const int wid = tid >> 5, lane = tid & 31, g = lane >> 2, t = lane & 3;
    const int lrow = lane & 7;
    const int boff = (lrow + ((lane >> 4) & 1) * 8) * 36 + ((lane >> 3) & 1) * 4;

    attn_stage(sm,                Kh, Vt, h, 0,  tid);
    CP_COMMIT();
    attn_stage(sm + ATTN_BUF_U32, Kh, Vt, h, 64, tid);
    CP_COMMIT();

    uint32_t ah[4][4];
    {
        const uint32_t* qh = Qh + ((size_t)h * NN + q0 + wid * 16 + g) * QKS;
        #pragma unroll
        for (int ks = 0; ks < 4; ks++) {
            ah[ks][0] = qh[ks * 8 + t];       ah[ks][1] = qh[8 * QKS + ks * 8 + t];
            ah[ks][2] = qh[ks * 8 + t + 4];   ah[ks][3] = qh[8 * QKS + ks * 8 + t + 4];
        }
    }

    float o[8][4] = {};
    float m0 = -1e30f, m1 = -1e30f, l0 = 0.f, l1 = 0.f;

    for (int tt = 0; tt < NN / 64; tt++) {
        if (tt < NN / 64 - 1) { CP_WAIT(1); } else { CP_WAIT(0); }
        __syncthreads();
        if (tt + 2 < NN / 64) {
            attn_stage(sm + ((tt + 2) % 3) * ATTN_BUF_U32, Kh, Vt, h, (tt + 2) * 64, tid);
            CP_COMMIT();
        }

        const uint32_t* buf = sm + (tt % 3) * ATTN_BUF_U32;
        const uint32_t* kh = buf;
        const uint32_t* vs = buf + 2304;

        float s[8][4] = {};
        #pragma unroll
        for (int ks = 0; ks < 4; ks++) {
            #pragma unroll
            for (int nbp = 0; nbp < 4; nbp++) {
                uint32_t b[4];
                ldsm_x4(b, kh + boff + nbp * 576 + ks * 8);
                mma_f16(s[2 * nbp],     ah[ks], b);
                mma_f16(s[2 * nbp + 1], ah[ks], b + 2);
            }
        }

        float mx0 = -1e30f, mx1 = -1e30f;
        #pragma unroll
        for (int nb = 0; nb < 8; nb++) {
            mx0 = fmaxf(mx0, fmaxf(s[nb][0], s[nb][1]));
            mx1 = fmaxf(mx1, fmaxf(s[nb][2], s[nb][3]));
        }
        mx0 = fmaxf(mx0, __shfl_xor_sync(0xffffffffu, mx0, 1));
        mx0 = fmaxf(mx0, __shfl_xor_sync(0xffffffffu, mx0, 2));
        mx1 = fmaxf(mx1, __shfl_xor_sync(0xffffffffu, mx1, 1));
        mx1 = fmaxf(mx1, __shfl_xor_sync(0xffffffffu, mx1, 2));

        float nm0 = fmaxf(m0, mx0), nm1 = fmaxf(m1, mx1);
        float sc0 = __expf(m0 - nm0), sc1 = __expf(m1 - nm1);
        float sum0 = 0.f, sum1 = 0.f;
        #pragma unroll
        for (int nb = 0; nb < 8; nb++) {
            s[nb][0] = __expf(s[nb][0] - nm0);
            s[nb][1] = __expf(s[nb][1] - nm0);
            s[nb][2] = __expf(s[nb][2] - nm1);
            s[nb][3] = __expf(s[nb][3] - nm1);
            sum0 += s[nb][0] + s[nb][1];
            sum1 += s[nb][2] + s[nb][3];
        }
        sum0 += __shfl_xor_sync(0xffffffffu, sum0, 1);
        sum0 += __shfl_xor_sync(0xffffffffu, sum0, 2);
        sum1 += __shfl_xor_sync(0xffffffffu, sum1, 1);
        sum1 += __shfl_xor_sync(0xffffffffu, sum1, 2);
        l0 = l0 * sc0 + sum0;  m0 = nm0;
        l1 = l1 * sc1 + sum1;  m1 = nm1;
        #pragma unroll
        for (int nb = 0; nb < 8; nb++) {
            o[nb][0] *= sc0; o[nb][1] *= sc0;
            o[nb][2] *= sc1; o[nb][3] *= sc1;
        }

        // O += P V (fp16)
        #pragma unroll
        for (int kp = 0; kp < 4; kp++) {
            uint32_t ap[4];
            ap[0] = pack2h(s[2 * kp][0],     s[2 * kp][1]);
            ap[1] = pack2h(s[2 * kp][2],     s[2 * kp][3]);
            ap[2] = pack2h(s[2 * kp + 1][0], s[2 * kp + 1][1]);
            ap[3] = pack2h(s[2 * kp + 1][2], s[2 * kp + 1][3]);
            #pragma unroll
            for (int nbp = 0; nbp < 4; nbp++) {
                uint32_t b[4];
                ldsm_x4(b, vs + boff + nbp * 576 + kp * 8);
                mma_f16(o[2 * nbp],     ap, b);
                mma_f16(o[2 * nbp + 1], ap, b + 2);
            }
        }
    }

    // epilogue: write concat as single fp16 pairs
    const float inv0 = 1.0f / l0, inv1 = 1.0f / l1;
    const int r0 = q0 + wid * 16 + g;
    #pragma unroll
    for (int nb = 0; nb < 8; nb++) {
        int cpi = h * 32 + nb * 4 + t;
        Ch[(size_t)r0 * 512 + cpi]       = pack2h(o[nb][0] * inv0, o[nb][1] * inv0);
        Ch[(size_t)(r0 + 8) * 512 + cpi] = pack2h(o[nb][2] * inv1, o[nb][3] * inv1);
    }
}

// ---------------------------------------------------------------------------
// LayerNorm, one block per row
// ---------------------------------------------------------------------------
__global__ void __launch_bounds__(256) ln_kernel(const float* __restrict__ pre,
                                                 const float* __restrict__ alpha,
                                                 const float* __restrict__ beta,
                                                 float* __restrict__ out)
{
    const int row = blockIdx.x;
    const int tid = threadIdx.x;
    const float4 v = ((const float4*)(pre + (size_t)row * DM))[tid];

    float sum = v.x + v.y + v.z + v.w;
    float sq  = v.x * v.x + v.y * v.y + v.z * v.z + v.w * v.w;

    #pragma unroll
    for (int d = 16; d >= 1; d >>= 1) {
        sum += __shfl_xor_sync(0xffffffffu, sum, d);
        sq  += __shfl_xor_sync(0xffffffffu, sq,  d);
    }

    __shared__ float ssum[8], ssq[8];
    __shared__ float s_mu, s_rstd;
    int warp = tid >> 5, lane = tid & 31;
    if (lane == 0) { ssum[warp] = sum; ssq[warp] = sq; }
    __syncthreads();
    if (tid == 0) {
        float ts = 0.f, tq = 0.f;
        #pragma unroll
        for (int i = 0; i < 8; i++) { ts += ssum[i]; tq += ssq[i]; }
        float mu  = ts * (1.0f / DM);
        float var = tq * (1.0f / DM) - mu * mu;
        s_mu = mu;
        s_rstd = rsqrtf(var + LN_EPS);
    }
    __syncthreads();

    const float mu = s_mu, rstd = s_rstd;
    const float4 a4 = ((const float4*)alpha)[tid];
    const float4 b4 = ((const float4*)beta)[tid];
    float4 r;
    r.x = a4.x * (v.x - mu) * rstd + b4.x;
    r.y = a4.y * (v.y - mu) * rstd + b4.y;
    r.z = a4.z * (v.z - mu) * rstd + b4.z;
    r.w = a4.w * (v.w - mu) * rstd + b4.w;
    ((float4*)(out + (size_t)row * DM))[tid] = r;
}

// ---------------------------------------------------------------------------
extern "C" void kernel_launch(void* const* d_in, const int* in_sizes, int n_in,
                              void* d_out, int out_size)
{
    const float* x     = (const float*)d_in[0];
    const float* wq    = (const float*)d_in[1];
    const float* qb    = (const float*)d_in[2];
    const float* wk    = (const float*)d_in[3];
    const float* kb    = (const float*)d_in[4];
    const float* wv    = (const float*)d_in[5];
    const float* vb    = (const float*)d_in[6];
    const float* wo    = (const float*)d_in[7];
    const float* ob    = (const float*)d_in[8];
    const float* alpha = (const float*)d_in[9];
    const float* beta  = (const float*)d_in[10];
    float* out = (float*)d_out;

    uint32_t *Xh, *Wq, *Wo;
    uint32_t *Qh, *Kh, *Vt, *Ch;
    float *pre;
    cudaGetSymbolAddress((void**)&Xh,  g_Xh);
    cudaGetSymbolAddress((void**)&Wq,  g_Wq);
    cudaGetSymbolAddress((void**)&Wo,  g_Wo);
    cudaGetSymbolAddress((void**)&Qh,  g_Qh);
    cudaGetSymbolAddress((void**)&Kh,  g_Kh);
    cudaGetSymbolAddress((void**)&Vt,  g_Vt);
    cudaGetSymbolAddress((void**)&Ch,  g_Ch);
    cudaGetSymbolAddress((void**)&pre, g_pre);

    cudaFuncSetAttribute(qkv_kernel,
                         cudaFuncAttributeMaxDynamicSharedMemorySize, G_SMEM);
    cudaFuncSetAttribute(outproj_kernel,
                         cudaFuncAttributeMaxDynamicSharedMemorySize, G_SMEM);
    cudaFuncSetAttribute(attn_kernel,
                         cudaFuncAttributeMaxDynamicSharedMemorySize, ATTN_SMEM_BYTES);

    // conversions (one fused launch)
    conv_all_kernel<<<NN + 768 + 256, 256>>>(x, wq, wk, wv, wo, Xh, Wq, Wo);

    qkv_kernel<<<dim3(NN / 128, NH, 3), 256, G_SMEM>>>(Xh, Wq,
                                                       qb, kb, vb,
                                                       Qh, Kh, Vt);

    attn_kernel<<<dim3(NN / 128, NH), 256, ATTN_SMEM_BYTES>>>(Qh, Kh, Vt, Ch);

    outproj_kernel<<<dim3(NN / 128, DM / 64), 256, G_SMEM>>>(Ch, Wo,
                                                             x, ob, pre);

    ln_kernel<<<NN, 256>>>(pre, alpha, beta, out);
}

// round 16
// speedup vs baseline: 1.5963x; 1.5963x over previous
#include <cuda_runtime.h>
#include <cuda_fp16.h>
#include <cstdint>

#define NN 2048
#define DM 1024
#define NH 16
#define DK 64
#define LN_EPS 1e-5f
#define QKS 36   // u32 row stride for packed Q/K (32 pairs + 4 pad)

// Scratch (device globals) — fp16 pair arrays (u32 = f16x2)
__device__ uint32_t g_Xh[(size_t)NN * 512];
__device__ uint32_t g_Wq[(size_t)NH * 192 * 512];     // single fp16
__device__ uint32_t g_Wo[(size_t)DM * 512];           // single fp16
__device__ uint32_t g_Qh[(size_t)NH * NN * QKS];      // single fp16 (pre-scaled)
__device__ uint32_t g_Kh[(size_t)NH * NN * QKS];      // single fp16
__device__ uint32_t g_Vt[(size_t)NH * DK * (NN / 2)]; // fp16 [h][dk][keypair]
__device__ uint32_t g_Ch[(size_t)NN * 512];           // concat, single fp16
__device__ float    g_pre[(size_t)NN * DM];

// ---------------------------------------------------------------------------
// helpers
// ---------------------------------------------------------------------------
__device__ __forceinline__ uint32_t pack2h(float e0, float e1) {  // f16x2: e0 low
    uint32_t r;
    asm("cvt.rn.f16x2.f32 %0, %1, %2;" : "=r"(r) : "f"(e1), "f"(e0));
    return r;
}
__device__ __forceinline__ uint16_t f16bits(float v) {
    uint16_t u;
    asm("cvt.rn.f16.f32 %0, %1;" : "=h"(u) : "f"(v));
    return u;
}
__device__ __forceinline__ void mma_f16(float* c, const uint32_t* a, const uint32_t* b) {
    asm("mma.sync.aligned.m16n8k16.row.col.f32.f16.f16.f32 "
        "{%0,%1,%2,%3}, {%4,%5,%6,%7}, {%8,%9}, {%0,%1,%2,%3};\n"
        : "+f"(c[0]), "+f"(c[1]), "+f"(c[2]), "+f"(c[3])
        : "r"(a[0]), "r"(a[1]), "r"(a[2]), "r"(a[3]), "r"(b[0]), "r"(b[1]));
}
__device__ __forceinline__ void ldsm_x4(uint32_t* r, const uint32_t* p) {
    uint32_t addr = (uint32_t)__cvta_generic_to_shared(p);
    asm volatile("ldmatrix.sync.aligned.m8n8.x4.shared.b16 {%0,%1,%2,%3}, [%4];"
        : "=r"(r[0]), "=r"(r[1]), "=r"(r[2]), "=r"(r[3]) : "r"(addr));
}
#define CPA16(sptr, gptr) do {                                                 \
    uint32_t _s = (uint32_t)__cvta_generic_to_shared(sptr);                    \
    asm volatile("cp.async.cg.shared.global [%0], [%1], 16;" :: "r"(_s), "l"(gptr)); \
} while (0)
#define CP_COMMIT() asm volatile("cp.async.commit_group;")
#define CP_WAIT(n)  asm volatile("cp.async.wait_group %0;" :: "n"(n))

// ---------------------------------------------------------------------------
// fused conversion kernel: one launch for x, wqkv, wo
// blocks [0, 2048): x rows; [2048, 2816): wqkv tiles; [2816, 3072): wo tiles
// ---------------------------------------------------------------------------
__global__ void __launch_bounds__(256) conv_all_kernel(const float* __restrict__ x,
                                                       const float* __restrict__ wq,
                                                       const float* __restrict__ wk,
                                                       const float* __restrict__ wv,
                                                       const float* __restrict__ wo,
                                                       uint32_t* __restrict__ Xh,
                                                       uint32_t* __restrict__ Wq,
                                                       uint32_t* __restrict__ Wo)
{
    __shared__ float sw[64][65];
    const int b = blockIdx.x;
    const int t = threadIdx.x;

    if (b < NN) {
        float4 v = ((const float4*)x)[b * 256 + t];
        Xh[(size_t)b * 512 + 2 * t]     = pack2h(v.x, v.y);
        Xh[(size_t)b * 512 + 2 * t + 1] = pack2h(v.z, v.w);
        return;
    }
    if (b < NN + 768) {
        const int z  = b - NN;
        const int k0 = (z & 15) * 64;
        const int w  = z >> 4;            // 0..47
        const int sec = w >> 4, h = w & 15;
        const float* s = (sec == 0 ? wq : sec == 1 ? wk : wv) + (size_t)h * DM * DK;

        #pragma unroll
        for (int i = 0; i < 16; i++) {
            int idx = i * 256 + t;
            int row = idx >> 6, col = idx & 63;
            sw[row][col] = s[(size_t)(k0 + row) * DK + col];
        }
        __syncthreads();
        #pragma unroll
        for (int i = 0; i < 8; i++) {
            int idx = i * 256 + t;
            int n = idx >> 5, kp = idx & 31;
            size_t o = (size_t)h * (192 * 512) + (size_t)(sec * 64 + n) * 512 + k0 / 2 + kp;
            Wq[o] = pack2h(sw[2 * kp][n], sw[2 * kp + 1][n]);
        }
        return;
    }
    {
        const int z  = b - NN - 768;
        const int k0 = (z & 15) * 64;
        const int n0 = (z >> 4) * 64;

        #pragma unroll
        for (int i = 0; i < 16; i++) {
            int idx = i * 256 + t;
            int row = idx >> 6, col = idx & 63;
            sw[row][col] = wo[(size_t)(k0 + row) * DM + n0 + col];
        }
        __syncthreads();
        #pragma unroll
        for (int i = 0; i < 8; i++) {
            int idx = i * 256 + t;
            int n = idx >> 5, kp = idx & 31;
            size_t o = (size_t)(n0 + n) * 512 + k0 / 2 + kp;
            Wo[o] = pack2h(sw[2 * kp][n], sw[2 * kp + 1][n]);
        }
    }
}

// ---------------------------------------------------------------------------
// GEMM tile machinery: 128 rows x 64 cols, k-chunk 64, 2-stage cp.async.
// Single-term fp16. Rows stored stride-36 u32 (32 data + 4 pad).
// Stage = A(128*36) + B(64*36) = 6912 u32; 2 stages = 55296 B.
// ---------------------------------------------------------------------------
#define G_STAGE_U32 6912
#define G_SMEM (2 * G_STAGE_U32 * 4)

__device__ __forceinline__ void gemm_stage_load(uint32_t* st,
                                                const uint32_t* Ag, const uint32_t* Bg,
                                                int kc32, int tid)
{
    #pragma unroll
    for (int i = 0; i < 4; i++) {
        int idx = tid + i * 256;               // 0..1023 : A rows 0..127
        int row = idx >> 3, blk = idx & 7;
        CPA16(st + row * 36 + blk * 4, Ag + (size_t)row * 512 + kc32 + blk * 4);
    }
    #pragma unroll
    for (int i = 0; i < 2; i++) {
        int idx = tid + i * 256;               // 0..511 : B rows 0..63
        int row = idx >> 3, blk = idx & 7;
        CPA16(st + 4608 + row * 36 + blk * 4, Bg + (size_t)row * 512 + kc32 + blk * 4);
    }
}

__device__ __forceinline__ void gemm_core(uint32_t* sm, float (*acc)[4],
                                          const uint32_t* Ag, const uint32_t* Bg,
                                          int tid, int aoff, int boff)
{
    gemm_stage_load(sm, Ag, Bg, 0, tid);
    CP_COMMIT();

    for (int c = 0; c < 16; c++) {
        if (c < 15) {
            gemm_stage_load(sm + ((c + 1) & 1) * G_STAGE_U32,
                            Ag, Bg, (c + 1) * 32, tid);
            CP_COMMIT();
            CP_WAIT(1);
        } else {
            CP_WAIT(0);
        }
        __syncthreads();

        const uint32_t* p  = sm + (c & 1) * G_STAGE_U32;
        const uint32_t* As = p;
        const uint32_t* Bs = p + 4608;

        #pragma unroll
        for (int ks = 0; ks < 4; ks++) {
            uint32_t a[4];
            ldsm_x4(a, As + aoff + ks * 8);
            #pragma unroll
            for (int nbp = 0; nbp < 4; nbp++) {
                uint32_t b[4];
                ldsm_x4(b, Bs + boff + nbp * 576 + ks * 8);
                mma_f16(acc[2 * nbp],     a, b);
                mma_f16(acc[2 * nbp + 1], a, b + 2);
            }
        }
        __syncthreads();
    }
}

// ---------------------------------------------------------------------------
// QKV GEMM: CTA = (row-tile, head, section). section: 0=Q, 1=K, 2=V.
// All single-term fp16; Q stored single fp16 (pre-scaled 0.125).
// ---------------------------------------------------------------------------
__global__ void __launch_bounds__(256, 3) qkv_kernel(const uint32_t* __restrict__ Xh,
                                                     const uint32_t* __restrict__ W,
                                                     const float* __restrict__ qb,
                                                     const float* __restrict__ kb,
                                                     const float* __restrict__ vb,
                                                     uint32_t* __restrict__ oQh,
                                                     uint32_t* __restrict__ oKh,
                                                     uint32_t* __restrict__ oVt)
{
    extern __shared__ uint32_t sm[];
    const int m0  = blockIdx.x * 128;
    const int h   = blockIdx.y;
    const int sec = blockIdx.z;
    const int tid = threadIdx.x;
    const int wid = tid >> 5, lane = tid & 31, g = lane >> 2, t = lane & 3;
    const int lrow = lane & 7;
    const int aoff = (wid * 16 + lrow + ((lane >> 3) & 1) * 8) * 36 + (lane >> 4) * 4;
    const int boff = (lrow + ((lane >> 4) & 1) * 8) * 36 + ((lane >> 3) & 1) * 4;

    float acc[8][4] = {};

    gemm_core(sm, acc,
              Xh + (size_t)m0 * 512,
              W + ((size_t)h * 192 + sec * 64) * 512,
              tid, aoff, boff);

    const int r = wid * 16 + g;
    const int grow = m0 + r;

    if (sec == 0) {
        // Q: single fp16, pre-scaled 0.125
        #pragma unroll
        for (int nb = 0; nb < 8; nb++) {
            int col = nb * 8 + 2 * t;
            float b0 = qb[h * DK + col], b1 = qb[h * DK + col + 1];
            size_t base = ((size_t)h * NN + grow) * QKS + nb * 4 + t;
            oQh[base]           = pack2h((acc[nb][0] + b0) * 0.125f, (acc[nb][1] + b1) * 0.125f);
            oQh[base + 8 * QKS] = pack2h((acc[nb][2] + b0) * 0.125f, (acc[nb][3] + b1) * 0.125f);
        }
    } else if (sec == 1) {
        // K: single fp16
        #pragma unroll
        for (int nb = 0; nb < 8; nb++) {
            int col = nb * 8 + 2 * t;
            float b0 = kb[h * DK + col], b1 = kb[h * DK + col + 1];
            size_t base = ((size_t)h * NN + grow) * QKS + nb * 4 + t;
            oKh[base]           = pack2h(acc[nb][0] + b0, acc[nb][1] + b1);
            oKh[base + 8 * QKS] = pack2h(acc[nb][2] + b0, acc[nb][3] + b1);
        }
    } else {
        // V: fp16 transpose via smem ([64 dk][132 fp16] = stride 66 u32)
        uint16_t* Vs16 = (uint16_t*)sm;
        #pragma unroll
        for (int nb = 0; nb < 8; nb++) {
            int col = nb * 8 + 2 * t;
            float b0 = vb[h * DK + col], b1 = vb[h * DK + col + 1];
            Vs16[(col)     * 132 + r]     = f16bits(acc[nb][0] + b0);
            Vs16[(col + 1) * 132 + r]     = f16bits(acc[nb][1] + b1);
            Vs16[(col)     * 132 + r + 8] = f16bits(acc[nb][2] + b0);
            Vs16[(col + 1) * 132 + r + 8] = f16bits(acc[nb][3] + b1);
        }
        __syncthreads();
        #pragma unroll
        for (int i = 0; i < 16; i++) {
            int idx = tid + i * 256;
            int dk = idx >> 6, cc = idx & 63;
            oVt[((size_t)h * DK + dk) * (NN / 2) + m0 / 2 + cc] = sm[dk * 66 + cc];
        }
    }
}

// ---------------------------------------------------------------------------
// Out projection + bias + residual: CTA = (row-tile, 64-col tile). 1-term.
// ---------------------------------------------------------------------------
__global__ void __launch_bounds__(256, 3) outproj_kernel(const uint32_t* __restrict__ Ag,
                                                         const uint32_t* __restrict__ Bg,
                                                         const float* __restrict__ x,
                                                         const float* __restrict__ ob,
                                                         float* __restrict__ out)
{
    extern __shared__ uint32_t sm[];
    const int m0 = blockIdx.x * 128;
    const int c0 = blockIdx.y * 64;
    const int tid = threadIdx.x;
    const int wid = tid >> 5, lane = tid & 31, g = lane >> 2, t = lane & 3;
    const int lrow = lane & 7;
    const int aoff = (wid * 16 + lrow + ((lane >> 3) & 1) * 8) * 36 + (lane >> 4) * 4;
    const int boff = (lrow + ((lane >> 4) & 1) * 8) * 36 + ((lane >> 3) & 1) * 4;

    float acc[8][4] = {};

    gemm_core(sm, acc,
              Ag + (size_t)m0 * 512,
              Bg + (size_t)c0 * 512,
              tid, aoff, boff);

    const int r0 = m0 + wid * 16 + g;
    #pragma unroll
    for (int nb = 0; nb < 8; nb++) {
        int col = c0 + nb * 8 + 2 * t;
        float b0 = ob[col], b1 = ob[col + 1];
        const float* xr0 = &x[(size_t)r0 * DM + col];
        const float* xr1 = &x[(size_t)(r0 + 8) * DM + col];
        float2 v0 = make_float2(acc[nb][0] + b0 + xr0[0], acc[nb][1] + b1 + xr0[1]);
        float2 v1 = make_float2(acc[nb][2] + b0 + xr1[0], acc[nb][3] + b1 + xr1[1]);
        *(float2*)&out[(size_t)r0 * DM + col]       = v0;
        *(float2*)&out[(size_t)(r0 + 8) * DM + col] = v1;
    }
}

// ---------------------------------------------------------------------------
// Flash attention: fp16 QK (single-term Q) + fp16 PV, 2-stage pipeline.
// buf = Kh[64][36] + Vt[64][36] = 4608 u32 per stage.
// ---------------------------------------------------------------------------
#define ATTN_BUF_U32 (2 * 64 * 36)
#define ATTN_SMEM_BYTES (2 * ATTN_BUF_U32 * 4)

__device__ __forceinline__ void attn_stage(uint32_t* dst, const uint32_t* Kh,
                                           const uint32_t* Vt,
                                           int h, int t0, int tid)
{
    const uint32_t* sKh = Kh + ((size_t)h * NN + t0) * QKS;
    const uint32_t* sVt = Vt + (size_t)h * DK * (NN / 2) + t0 / 2;
    for (int idx = tid; idx < 1088; idx += 256) {
        if (idx < 576) {
            CPA16(dst + idx * 4, sKh + idx * 4);
        } else {
            int j = idx - 576;
            int dk = j >> 3, c = (j & 7) * 4;
            CPA16(dst + 2304 + dk * 36 + c, sVt + (size_t)dk * (NN / 2) + c);
        }
    }
}

__global__ void __launch_bounds__(256, 2) attn_kernel(const uint32_t* __restrict__ Qh,
                                                      const uint32_t* __restrict__ Kh,
                                                      const uint32_t* __restrict__ Vt,
                                                      uint32_t* __restrict__ Ch)
{
    extern __shared__ uint32_t sm[];
    const int h  = blockIdx.y;
    const int q0 = blockIdx.x * 128;
    const int tid = threadIdx.x;
    const int wid = tid >> 5, lane = tid & 31, g = lane >> 2, t = lane & 3;
    const int lrow = lane & 7;
    const int boff = (lrow + ((lane >> 4) & 1) * 8) * 36 + ((lane >> 3) & 1) * 4;

    attn_stage(sm, Kh, Vt, h, 0, tid);
    CP_COMMIT();

    uint32_t ah[4][4];
    {
        const uint32_t* qh = Qh + ((size_t)h * NN + q0 + wid * 16 + g) * QKS;
        #pragma unroll
        for (int ks = 0; ks < 4; ks++) {
            ah[ks][0] = qh[ks * 8 + t];       ah[ks][1] = qh[8 * QKS + ks * 8 + t];
            ah[ks][2] = qh[ks * 8 + t + 4];   ah[ks][3] = qh[8 * QKS + ks * 8 + t + 4];
        }
    }

    float o[8][4] = {};
    float m0 = -1e30f, m1 = -1e30f, l0 = 0.f, l1 = 0.f;

    for (int tt = 0; tt < NN / 64; tt++) {
        uint32_t* buf = sm + (tt & 1) * ATTN_BUF_U32;
        if (tt + 1 < NN / 64) {
            attn_stage(sm + ((tt + 1) & 1) * ATTN_BUF_U32, Kh, Vt, h, (tt + 1) * 64, tid);
            CP_COMMIT();
            CP_WAIT(1);
        } else {
            CP_WAIT(0);
        }
        __syncthreads();

        const uint32_t* kh = buf;
        const uint32_t* vs = buf + 2304;

        float s[8][4] = {};
        #pragma unroll
        for (int ks = 0; ks < 4; ks++) {
            #pragma unroll
            for (int nbp = 0; nbp < 4; nbp++) {
                uint32_t b[4];
                ldsm_x4(b, kh + boff + nbp * 576 + ks * 8);
                mma_f16(s[2 * nbp],     ah[ks], b);
                mma_f16(s[2 * nbp + 1], ah[ks], b + 2);
            }
        }

        float mx0 = -1e30f, mx1 = -1e30f;
        #pragma unroll
        for (int nb = 0; nb < 8; nb++) {
            mx0 = fmaxf(mx0, fmaxf(s[nb][0], s[nb][1]));
            mx1 = fmaxf(mx1, fmaxf(s[nb][2], s[nb][3]));
        }
        mx0 = fmaxf(mx0, __shfl_xor_sync(0xffffffffu, mx0, 1));
        mx0 = fmaxf(mx0, __shfl_xor_sync(0xffffffffu, mx0, 2));
        mx1 = fmaxf(mx1, __shfl_xor_sync(0xffffffffu, mx1, 1));
        mx1 = fmaxf(mx1, __shfl_xor_sync(0xffffffffu, mx1, 2));

        float nm0 = fmaxf(m0, mx0), nm1 = fmaxf(m1, mx1);
        float sc0 = __expf(m0 - nm0), sc1 = __expf(m1 - nm1);
        float sum0 = 0.f, sum1 = 0.f;
        #pragma unroll
        for (int nb = 0; nb < 8; nb++) {
            s[nb][0] = __expf(s[nb][0] - nm0);
            s[nb][1] = __expf(s[nb][1] - nm0);
            s[nb][2] = __expf(s[nb][2] - nm1);
            s[nb][3] = __expf(s[nb][3] - nm1);
            sum0 += s[nb][0] + s[nb][1];
            sum1 += s[nb][2] + s[nb][3];
        }
        sum0 += __shfl_xor_sync(0xffffffffu, sum0, 1);
        sum0 += __shfl_xor_sync(0xffffffffu, sum0, 2);
        sum1 += __shfl_xor_sync(0xffffffffu, sum1, 1);
        sum1 += __shfl_xor_sync(0xffffffffu, sum1, 2);
        l0 = l0 * sc0 + sum0;  m0 = nm0;
        l1 = l1 * sc1 + sum1;  m1 = nm1;
        #pragma unroll
        for (int nb = 0; nb < 8; nb++) {
            o[nb][0] *= sc0; o[nb][1] *= sc0;
            o[nb][2] *= sc1; o[nb][3] *= sc1;
        }

        // O += P V (fp16)
        #pragma unroll
        for (int kp = 0; kp < 4; kp++) {
            uint32_t ap[4];
            ap[0] = pack2h(s[2 * kp][0],     s[2 * kp][1]);
            ap[1] = pack2h(s[2 * kp][2],     s[2 * kp][3]);
            ap[2] = pack2h(s[2 * kp + 1][0], s[2 * kp + 1][1]);
            ap[3] = pack2h(s[2 * kp + 1][2], s[2 * kp + 1][3]);
            #pragma unroll
            for (int nbp = 0; nbp < 4; nbp++) {
                uint32_t b[4];
                ldsm_x4(b, vs + boff + nbp * 576 + kp * 8);
                mma_f16(o[2 * nbp],     ap, b);
                mma_f16(o[2 * nbp + 1], ap, b + 2);
            }
        }
        __syncthreads();
    }

    // epilogue: write concat as single fp16 pairs
    const float inv0 = 1.0f / l0, inv1 = 1.0f / l1;
    const int r0 = q0 + wid * 16 + g;
    #pragma unroll
    for (int nb = 0; nb < 8; nb++) {
        int cpi = h * 32 + nb * 4 + t;
        Ch[(size_t)r0 * 512 + cpi]       = pack2h(o[nb][0] * inv0, o[nb][1] * inv0);
        Ch[(size_t)(r0 + 8) * 512 + cpi] = pack2h(o[nb][2] * inv1, o[nb][3] * inv1);
    }
}

// ---------------------------------------------------------------------------
// LayerNorm, one block per row
// ---------------------------------------------------------------------------
__global__ void __launch_bounds__(256) ln_kernel(const float* __restrict__ pre,
                                                 const float* __restrict__ alpha,
                                                 const float* __restrict__ beta,
                                                 float* __restrict__ out)
{
    const int row = blockIdx.x;
    const int tid = threadIdx.x;
    const float4 v = ((const float4*)(pre + (size_t)row * DM))[tid];

    float sum = v.x + v.y + v.z + v.w;
    float sq  = v.x * v.x + v.y * v.y + v.z * v.z + v.w * v.w;

    #pragma unroll
    for (int d = 16; d >= 1; d >>= 1) {
        sum += __shfl_xor_sync(0xffffffffu, sum, d);
        sq  += __shfl_xor_sync(0xffffffffu, sq,  d);
    }

    __shared__ float ssum[8], ssq[8];
    __shared__ float s_mu, s_rstd;
    int warp = tid >> 5, lane = tid & 31;
    if (lane == 0) { ssum[warp] = sum; ssq[warp] = sq; }
    __syncthreads();
    if (tid == 0) {
        float ts = 0.f, tq = 0.f;
        #pragma unroll
        for (int i = 0; i < 8; i++) { ts += ssum[i]; tq += ssq[i]; }
        float mu  = ts * (1.0f / DM);
        float var = tq * (1.0f / DM) - mu * mu;
        s_mu = mu;
        s_rstd = rsqrtf(var + LN_EPS);
    }
    __syncthreads();

    const float mu = s_mu, rstd = s_rstd;
    const float4 a4 = ((const float4*)alpha)[tid];
    const float4 b4 = ((const float4*)beta)[tid];
    float4 r;
    r.x = a4.x * (v.x - mu) * rstd + b4.x;
    r.y = a4.y * (v.y - mu) * rstd + b4.y;
    r.z = a4.z * (v.z - mu) * rstd + b4.z;
    r.w = a4.w * (v.w - mu) * rstd + b4.w;
    ((float4*)(out + (size_t)row * DM))[tid] = r;
}

// ---------------------------------------------------------------------------
extern "C" void kernel_launch(void* const* d_in, const int* in_sizes, int n_in,
                              void* d_out, int out_size)
{
    const float* x     = (const float*)d_in[0];
    const float* wq    = (const float*)d_in[1];
    const float* qb    = (const float*)d_in[2];
    const float* wk    = (const float*)d_in[3];
    const float* kb    = (const float*)d_in[4];
    const float* wv    = (const float*)d_in[5];
    const float* vb    = (const float*)d_in[6];
    const float* wo    = (const float*)d_in[7];
    const float* ob    = (const float*)d_in[8];
    const float* alpha = (const float*)d_in[9];
    const float* beta  = (const float*)d_in[10];
    float* out = (float*)d_out;

    uint32_t *Xh, *Wq, *Wo;
    uint32_t *Qh, *Kh, *Vt, *Ch;
    float *pre;
    cudaGetSymbolAddress((void**)&Xh,  g_Xh);
    cudaGetSymbolAddress((void**)&Wq,  g_Wq);
    cudaGetSymbolAddress((void**)&Wo,  g_Wo);
    cudaGetSymbolAddress((void**)&Qh,  g_Qh);
    cudaGetSymbolAddress((void**)&Kh,  g_Kh);
    cudaGetSymbolAddress((void**)&Vt,  g_Vt);
    cudaGetSymbolAddress((void**)&Ch,  g_Ch);
    cudaGetSymbolAddress((void**)&pre, g_pre);

    cudaFuncSetAttribute(qkv_kernel,
                         cudaFuncAttributeMaxDynamicSharedMemorySize, G_SMEM);
    cudaFuncSetAttribute(outproj_kernel,
                         cudaFuncAttributeMaxDynamicSharedMemorySize, G_SMEM);
    cudaFuncSetAttribute(attn_kernel,
                         cudaFuncAttributeMaxDynamicSharedMemorySize, ATTN_SMEM_BYTES);

    // conversions (one fused launch)
    conv_all_kernel<<<NN + 768 + 256, 256>>>(x, wq, wk, wv, wo, Xh, Wq, Wo);

    qkv_kernel<<<dim3(NN / 128, NH, 3), 256, G_SMEM>>>(Xh, Wq,
                                                       qb, kb, vb,
                                                       Qh, Kh, Vt);

    attn_kernel<<<dim3(NN / 128, NH), 256, ATTN_SMEM_BYTES>>>(Qh, Kh, Vt, Ch);

    outproj_kernel<<<dim3(NN / 128, DM / 64), 256, G_SMEM>>>(Ch, Wo,
                                                             x, ob, pre);

    ln_kernel<<<NN, 256>>>(pre, alpha, beta, out);
}